// round 5
// baseline (speedup 1.0000x reference)
#include <cuda_runtime.h>

typedef unsigned long long ull;

#define NLOC 4096
#define NNEI 120
#define TOK  4
#define PAD  132
#define RSQRT_ND 0.17677669529663687f  /* 1/sqrt(32) */
#define SHIFT 20.0f

// smem float offsets (per CTA)
#define GG    0                 // 15840 : gg1 tile (120 x PAD)
#define G1P   15840             // 512  : g1 packed [m][t]
#define SWS   16352             // 480  : [t][n]
#define QES   16832             // 2048 : [t][i][h]
#define CS    18880             // 2048 : [f][t]  (t fast, stride 4)
#define SCP   20928             // 960  : qa*480 + h*120 + n
#define AW    21888             // 512  : n*4 + h
#define SMEMF 22400             // 89.6 KB
// OUTP reuses GG (tile dead at out-GEMM): fh*512 + t*128 + o

// Folded weights, rebuilt every launch (deterministic).
__device__ float d_Wqk[4 * 128 * 128];    // [h][m][i]
__device__ float d_Wfold[512 * 128];      // [(h*128+j)][o]

__global__ void prep_kernel(const float* __restrict__ Wq,
                            const float* __restrict__ Wkv,
                            const float* __restrict__ Wh) {
    int idx = blockIdx.x * blockDim.x + threadIdx.x;
    if (idx < 65536) {
        // Wqk[h][m][i] = sum_d Wq[m, d*4+h] * Wkv[i, d*4+h]
        int h = idx >> 14;
        int m = (idx >> 7) & 127;
        int i = idx & 127;
        float acc = 0.f;
#pragma unroll
        for (int d = 0; d < 32; d++)
            acc = fmaf(Wq[m * 128 + d * 4 + h], Wkv[i * 640 + d * 4 + h], acc);
        d_Wqk[idx] = acc;
    } else {
        // Wfold[h*128+j][o] = sum_i Wkv[j, (32+i)*4+h] * Wh[h*128+i, o]
        int z = idx - 65536;
        int r = z >> 7;        // h*128 + j
        int o = z & 127;
        int h = r >> 7;
        int j = r & 127;
        float acc = 0.f;
#pragma unroll 8
        for (int i = 0; i < 128; i++)
            acc = fmaf(Wkv[j * 640 + (32 + i) * 4 + h], Wh[(h * 128 + i) * 128 + o], acc);
        d_Wfold[z] = acc;
    }
}

__device__ __forceinline__ ull pk2(float x, float y) {
    ull r; asm("mov.b64 %0, {%1, %2};" : "=l"(r) : "f"(x), "f"(y)); return r;
}
__device__ __forceinline__ void upk2(ull v, float& x, float& y) {
    asm("mov.b64 {%0, %1}, %2;" : "=f"(x), "=f"(y) : "l"(v));
}
__device__ __forceinline__ ull ffma2(ull a, ull b, ull c) {
    ull d; asm("fma.rn.f32x2 %0, %1, %2, %3;" : "=l"(d) : "l"(a), "l"(b), "l"(c)); return d;
}

__global__ __launch_bounds__(256, 2)
void atten_kernel(const float* __restrict__ g1,
                  const float* __restrict__ gg1,
                  const float* __restrict__ sw,
                  const float* __restrict__ bh,
                  float* __restrict__ out) {
    extern __shared__ float s[];
    const int tid  = threadIdx.x;
    const int l0   = blockIdx.x * TOK;
    const int lane = tid & 31;
    const int wrp  = tid >> 5;

    // ---- g1 packed [m][t], sw [t][n] ----
    for (int idx = tid; idx < TOK * 128; idx += 256) {
        int t = idx >> 7, m = idx & 127;
        s[G1P + m * 4 + t] = g1[(l0 + t) * 128 + m];
    }
    for (int idx = tid; idx < TOK * NNEI; idx += 256)
        s[SWS + idx] = sw[l0 * NNEI + idx];
    __syncthreads();

    // ---- Q: qe[t][h][i] = g1[t] . Wqk[h][:,i]; token-pairs via f32x2, 2 heads/thread ----
    {
        int h0 = tid >> 7, i = tid & 127;            // h0 in {0,1}; handles h0, h0+2
        const float* wa = d_Wqk + h0 * 16384 + i;
        const float* wb = d_Wqk + (h0 + 2) * 16384 + i;
        ull a0 = 0, a1 = 0, b0 = 0, b1 = 0;
#pragma unroll 4
        for (int m = 0; m < 128; m++) {
            float wA = wa[m * 128];
            float wB = wb[m * 128];
            const ull* gp = reinterpret_cast<const ull*>(s + G1P + m * 4);
            ull g01 = gp[0], g23 = gp[1];
            ull wA2 = pk2(wA, wA), wB2 = pk2(wB, wB);
            a0 = ffma2(wA2, g01, a0);
            a1 = ffma2(wA2, g23, a1);
            b0 = ffma2(wB2, g01, b0);
            b1 = ffma2(wB2, g23, b1);
        }
        float x, y;
        upk2(a0, x, y); s[QES + 0 * 512 + i * 4 + h0] = x; s[QES + 1 * 512 + i * 4 + h0] = y;
        upk2(a1, x, y); s[QES + 2 * 512 + i * 4 + h0] = x; s[QES + 3 * 512 + i * 4 + h0] = y;
        upk2(b0, x, y); s[QES + 0 * 512 + i * 4 + h0 + 2] = x; s[QES + 1 * 512 + i * 4 + h0 + 2] = y;
        upk2(b1, x, y); s[QES + 2 * 512 + i * 4 + h0 + 2] = x; s[QES + 3 * 512 + i * 4 + h0 + 2] = y;
    }
    __syncthreads();

    for (int t = 0; t < TOK; t++) {

        // ---- load tile (120x128 f32) : 15 float4 per thread, coalesced ----
        {
            const float4* gsrc = reinterpret_cast<const float4*>(gg1 + (size_t)(l0 + t) * 15360);
#pragma unroll
            for (int p = 0; p < 15; p++) {
                int q = tid + p * 256;
                float4 v = gsrc[q];
                int n = q >> 5, j4 = (q & 31) << 2;
                *reinterpret_cast<float4*>(s + GG + n * PAD + j4) = v;
            }
        }
        __syncthreads();

        // ---- scores partials: thread (n, half qa): 64 j's, 4 heads via f32x2 ----
        if (tid < 240) {
            int n = tid % 120, qa = tid / 120;
            const float* grow = s + GG + n * PAD + qa * 64;
            const ull* qrow = reinterpret_cast<const ull*>(s + QES + t * 512 + qa * 256);
            ull s01 = 0, s23 = 0;
#pragma unroll
            for (int jq = 0; jq < 16; jq++) {
                float4 g4 = *reinterpret_cast<const float4*>(grow + jq * 4);
                ull g2;
                g2 = pk2(g4.x, g4.x);
                s01 = ffma2(g2, qrow[(jq * 4 + 0) * 2],     s01);
                s23 = ffma2(g2, qrow[(jq * 4 + 0) * 2 + 1], s23);
                g2 = pk2(g4.y, g4.y);
                s01 = ffma2(g2, qrow[(jq * 4 + 1) * 2],     s01);
                s23 = ffma2(g2, qrow[(jq * 4 + 1) * 2 + 1], s23);
                g2 = pk2(g4.z, g4.z);
                s01 = ffma2(g2, qrow[(jq * 4 + 2) * 2],     s01);
                s23 = ffma2(g2, qrow[(jq * 4 + 2) * 2 + 1], s23);
                g2 = pk2(g4.w, g4.w);
                s01 = ffma2(g2, qrow[(jq * 4 + 3) * 2],     s01);
                s23 = ffma2(g2, qrow[(jq * 4 + 3) * 2 + 1], s23);
            }
            float x, y;
            float* sp = s + SCP + qa * 480;
            upk2(s01, x, y); sp[0 * 120 + n] = x; sp[1 * 120 + n] = y;
            upk2(s23, x, y); sp[2 * 120 + n] = x; sp[3 * 120 + n] = y;
        }
        __syncthreads();

        // ---- softmax: warp h handles head h ----
        if (wrp < 4) {
            int h = wrp;
            const float* sp = s + SCP;
            float vv[4];
            float mx = -1e30f;
#pragma unroll
            for (int kk = 0; kk < 4; kk++) {
                int n = lane + kk * 32;
                if (n < NNEI) {
                    float sc = sp[h * 120 + n] + sp[480 + h * 120 + n];
                    sc *= RSQRT_ND;
                    sc = (sc + SHIFT) * s[SWS + t * NNEI + n] - SHIFT;
                    vv[kk] = sc;
                    mx = fmaxf(mx, sc);
                } else vv[kk] = -1e30f;
            }
#pragma unroll
            for (int o = 16; o; o >>= 1) mx = fmaxf(mx, __shfl_xor_sync(0xffffffffu, mx, o));
            float sum = 0.f;
#pragma unroll
            for (int kk = 0; kk < 4; kk++) { vv[kk] = __expf(vv[kk] - mx); sum += vv[kk]; }
#pragma unroll
            for (int o = 16; o; o >>= 1) sum += __shfl_xor_sync(0xffffffffu, sum, o);
            float inv = 1.f / sum;
#pragma unroll
            for (int kk = 0; kk < 4; kk++) {
                int n = lane + kk * 32;
                if (n < NNEI) s[AW + n * 4 + h] = vv[kk] * inv * s[SWS + t * NNEI + n];
            }
        }
        __syncthreads();

        // ---- c-phase: thread (j-pair j2 = tid>>2, n-quarter nq = tid&3); 30 n each;
        //      tile element read ONCE, 4 head-accs; quad-shfl reduction ----
        {
            int j2 = tid >> 2, nq = tid & 3;
            ull aA0 = 0, aA1 = 0, aB0 = 0, aB1 = 0;
            int n0 = nq * 30;
#pragma unroll 6
            for (int ii = 0; ii < 30; ii++) {
                int n = n0 + ii;
                ull g = *reinterpret_cast<const ull*>(s + GG + n * PAD + j2 * 2);
                float gA, gB; upk2(g, gA, gB);
                const ull* awp = reinterpret_cast<const ull*>(s + AW + n * 4);
                ull w01 = awp[0], w23 = awp[1];
                ull gA2 = pk2(gA, gA), gB2 = pk2(gB, gB);
                aA0 = ffma2(gA2, w01, aA0); aA1 = ffma2(gA2, w23, aA1);
                aB0 = ffma2(gB2, w01, aB0); aB1 = ffma2(gB2, w23, aB1);
            }
            float a[8];
            upk2(aA0, a[0], a[1]); upk2(aA1, a[2], a[3]);
            upk2(aB0, a[4], a[5]); upk2(aB1, a[6], a[7]);
#pragma unroll
            for (int d = 2; d; d >>= 1)
#pragma unroll
                for (int q = 0; q < 8; q++)
                    a[q] += __shfl_down_sync(0xffffffffu, a[q], d, 4);
            if (nq == 0) {
                int jA = j2 * 2, jB = jA + 1;
                s[CS + (0 * 128 + jA) * 4 + t] = a[0];
                s[CS + (1 * 128 + jA) * 4 + t] = a[1];
                s[CS + (2 * 128 + jA) * 4 + t] = a[2];
                s[CS + (3 * 128 + jA) * 4 + t] = a[3];
                s[CS + (0 * 128 + jB) * 4 + t] = a[4];
                s[CS + (1 * 128 + jB) * 4 + t] = a[5];
                s[CS + (2 * 128 + jB) * 4 + t] = a[6];
                s[CS + (3 * 128 + jB) * 4 + t] = a[7];
            }
        }
        __syncthreads();  // tile free for next t; cs[.][t] written
    }

    // ---- out GEMM: out[t] = bh + cs[t] @ Wfold; token-pairs via f32x2; partials in tile space ----
    {
        int o = tid & 127, fh = tid >> 7;            // fh in {0,1}: 256 f-values each
        ull a0 = 0, a1 = 0;
        const float* wp = d_Wfold + fh * 256 * 128 + o;
#pragma unroll 4
        for (int ff = 0; ff < 256; ff++) {
            float w = wp[ff * 128];
            ull w2 = pk2(w, w);
            const ull* cp = reinterpret_cast<const ull*>(s + CS + (fh * 256 + ff) * 4);
            a0 = ffma2(w2, cp[0], a0);
            a1 = ffma2(w2, cp[1], a1);
        }
        float x, y;
        upk2(a0, x, y); s[fh * 512 + 0 * 128 + o] = x; s[fh * 512 + 1 * 128 + o] = y;
        upk2(a1, x, y); s[fh * 512 + 2 * 128 + o] = x; s[fh * 512 + 3 * 128 + o] = y;
    }
    __syncthreads();
#pragma unroll
    for (int rr = 0; rr < 2; rr++) {
        int idx = tid + rr * 256;
        int t = idx >> 7, o = idx & 127;
        float v = bh[o] + s[0 * 512 + t * 128 + o] + s[1 * 512 + t * 128 + o];
        out[(size_t)(l0 + t) * 128 + o] = v;
    }
}

extern "C" void kernel_launch(void* const* d_in, const int* in_sizes, int n_in,
                              void* d_out, int out_size) {
    const float* g1  = (const float*)d_in[0];
    const float* gg1 = (const float*)d_in[1];
    // d_in[2] = nlist_mask: redundant (sw == uniform * mask)
    const float* sw  = (const float*)d_in[3];
    const float* Wq  = (const float*)d_in[4];
    const float* Wkv = (const float*)d_in[5];
    const float* Wh  = (const float*)d_in[6];
    const float* bh  = (const float*)d_in[7];
    float* out = (float*)d_out;

    const size_t SMEM = (size_t)SMEMF * sizeof(float);  // 89.6 KB

    cudaFuncSetAttribute((const void*)atten_kernel,
                         cudaFuncAttributeMaxDynamicSharedMemorySize, (int)SMEM);

    prep_kernel<<<512, 256>>>(Wq, Wkv, Wh);
    atten_kernel<<<NLOC / TOK, 256, SMEM>>>(g1, gg1, sw, bh, out);
}

// round 6
// speedup vs baseline: 1.0194x; 1.0194x over previous
#include <cuda_runtime.h>

typedef unsigned long long ull;

#define NLOC 4096
#define NNEI 120
#define RSQRT_ND 0.17677669529663687f  /* 1/sqrt(32) */
#define SHIFT 20.0f

// smem float offsets for atten_kernel (per CTA, dynamic)
#define GG    0                 // 120*132 = 15840 : gg1 tile [n][j], rows padded to 132
#define QE    15840             // 4*132  = 528    : q [h][j], rows padded to 132
#define SW    16368             // 120
#define SCP   16488             // 960 : qa*480 + h*120 + n
#define AW    17448             // 960 : [n][8] = 4 heads x duplicated (w,w) pairs
#define SMEMF 18408             // 73632 B

// Globals (static device arrays; no allocation)
__device__ float d_Wqk[4 * 128 * 128];    // [h][m][i]
__device__ float d_Wfold[512 * 128];      // [(h*128+j)][o]
__device__ float d_qe[NLOC * 512];        // [t][h*128+i]
__device__ float d_C[NLOC * 512];         // [t][h*128+j]

__device__ __forceinline__ ull pk2(float x, float y) {
    ull r; asm("mov.b64 %0, {%1, %2};" : "=l"(r) : "f"(x), "f"(y)); return r;
}
__device__ __forceinline__ void upk2(ull v, float& x, float& y) {
    asm("mov.b64 {%0, %1}, %2;" : "=f"(x), "=f"(y) : "l"(v));
}
__device__ __forceinline__ ull ffma2(ull a, ull b, ull c) {
    ull d; asm("fma.rn.f32x2 %0, %1, %2, %3;" : "=l"(d) : "l"(a), "l"(b), "l"(c)); return d;
}

// ---------------- kernel 1: fold weights ----------------
__global__ void prep_kernel(const float* __restrict__ Wq,
                            const float* __restrict__ Wkv,
                            const float* __restrict__ Wh) {
    int idx = blockIdx.x * blockDim.x + threadIdx.x;
    if (idx < 65536) {
        // Wqk[h][m][i] = sum_d Wq[m, d*4+h] * Wkv[i, d*4+h]
        int h = idx >> 14;
        int m = (idx >> 7) & 127;
        int i = idx & 127;
        float acc = 0.f;
#pragma unroll
        for (int d = 0; d < 32; d++)
            acc = fmaf(Wq[m * 128 + d * 4 + h], Wkv[i * 640 + d * 4 + h], acc);
        d_Wqk[idx] = acc;
    } else {
        // Wfold[h*128+j][o] = sum_i Wkv[j, (32+i)*4+h] * Wh[h*128+i, o]
        int z = idx - 65536;
        int r = z >> 7;
        int o = z & 127;
        int h = r >> 7;
        int j = r & 127;
        float acc = 0.f;
#pragma unroll 8
        for (int i = 0; i < 128; i++)
            acc = fmaf(Wkv[j * 640 + (32 + i) * 4 + h], Wh[(h * 128 + i) * 128 + o], acc);
        d_Wfold[z] = acc;
    }
}

// ---------------- kernel 2: qe = g1 @ Wqk for all tokens ----------------
// grid 256, 512 threads, 16 tokens per CTA; thread = output col c = h*128+i
__global__ __launch_bounds__(512) void qe_kernel(const float* __restrict__ g1) {
    __shared__ float g1s[128 * 16];   // [m][t]
    const int t0  = blockIdx.x * 16;
    const int tid = threadIdx.x;
    for (int idx = tid; idx < 2048; idx += 512) {
        int t = idx >> 7, m = idx & 127;
        g1s[m * 16 + t] = g1[(t0 + t) * 128 + m];
    }
    __syncthreads();
    const int h = tid >> 7, i = tid & 127;
    const float* wb = d_Wqk + h * 16384 + i;
    ull a[8];
#pragma unroll
    for (int k = 0; k < 8; k++) a[k] = 0;
#pragma unroll 4
    for (int m = 0; m < 128; m++) {
        float w = wb[m * 128];
        ull w2 = pk2(w, w);
        const ull* gp = reinterpret_cast<const ull*>(g1s + m * 16);
#pragma unroll
        for (int k = 0; k < 8; k++) a[k] = ffma2(w2, gp[k], a[k]);
    }
#pragma unroll
    for (int k = 0; k < 8; k++) {
        float x, y; upk2(a[k], x, y);
        d_qe[(size_t)(t0 + 2 * k) * 512 + tid]     = x;
        d_qe[(size_t)(t0 + 2 * k + 1) * 512 + tid] = y;
    }
}

// ---------------- kernel 3: attention core, 1 token per CTA ----------------
__global__ __launch_bounds__(256, 3)
void atten_kernel(const float* __restrict__ gg1,
                  const float* __restrict__ sw) {
    extern __shared__ float s[];
    const int tid  = threadIdx.x;
    const int t    = blockIdx.x;
    const int lane = tid & 31;
    const int wrp  = tid >> 5;

    // q tile [h][132-padded j] + sw
    if (tid < 128) {
        float4 v = *reinterpret_cast<const float4*>(d_qe + (size_t)t * 512 + tid * 4);
        int h = (tid * 4) >> 7, i = (tid * 4) & 127;
        *reinterpret_cast<float4*>(s + QE + h * 132 + i) = v;
    }
    if (tid < NNEI) s[SW + tid] = sw[(size_t)t * NNEI + tid];

    // gg1 tile: 15 float4 per thread, coalesced; front-batched LDGs
    {
        const float4* gsrc = reinterpret_cast<const float4*>(gg1 + (size_t)t * 15360);
#pragma unroll
        for (int p = 0; p < 15; p++) {
            int q = tid + p * 256;
            float4 v = gsrc[q];
            int n = q >> 5, j4 = (q & 31) << 2;
            *reinterpret_cast<float4*>(s + GG + n * 132 + j4) = v;
        }
    }
    __syncthreads();

    // ---- scores: thread (n, qa half of j); natural 64-bit pairs, no packing movs ----
    if (tid < 240) {
        int qa = (tid >= 120) ? 1 : 0;
        int n  = tid - qa * 120;
        const ulonglong2* g2 = reinterpret_cast<const ulonglong2*>(s + GG + n * 132 + qa * 64);
        const ulonglong2* q0 = reinterpret_cast<const ulonglong2*>(s + QE + 0 * 132 + qa * 64);
        const ulonglong2* q1 = reinterpret_cast<const ulonglong2*>(s + QE + 1 * 132 + qa * 64);
        const ulonglong2* q2 = reinterpret_cast<const ulonglong2*>(s + QE + 2 * 132 + qa * 64);
        const ulonglong2* q3 = reinterpret_cast<const ulonglong2*>(s + QE + 3 * 132 + qa * 64);
        ull a0 = 0, a1 = 0, a2 = 0, a3 = 0;
#pragma unroll
        for (int jq = 0; jq < 16; jq++) {
            ulonglong2 g = g2[jq];
            ulonglong2 qh;
            qh = q0[jq]; a0 = ffma2(g.x, qh.x, a0); a0 = ffma2(g.y, qh.y, a0);
            qh = q1[jq]; a1 = ffma2(g.x, qh.x, a1); a1 = ffma2(g.y, qh.y, a1);
            qh = q2[jq]; a2 = ffma2(g.x, qh.x, a2); a2 = ffma2(g.y, qh.y, a2);
            qh = q3[jq]; a3 = ffma2(g.x, qh.x, a3); a3 = ffma2(g.y, qh.y, a3);
        }
        float x, y;
        float* sp = s + SCP + qa * 480;
        upk2(a0, x, y); sp[0 * 120 + n] = x + y;
        upk2(a1, x, y); sp[1 * 120 + n] = x + y;
        upk2(a2, x, y); sp[2 * 120 + n] = x + y;
        upk2(a3, x, y); sp[3 * 120 + n] = x + y;
    }
    __syncthreads();

    // ---- softmax: warp h handles head h; writes duplicated (w,w) pairs ----
    if (wrp < 4) {
        int h = wrp;
        float vv[4];
        float mx = -1e30f;
#pragma unroll
        for (int kk = 0; kk < 4; kk++) {
            int n = lane + kk * 32;
            if (n < NNEI) {
                float sc = s[SCP + h * 120 + n] + s[SCP + 480 + h * 120 + n];
                sc *= RSQRT_ND;
                sc = (sc + SHIFT) * s[SW + n] - SHIFT;
                vv[kk] = sc;
                mx = fmaxf(mx, sc);
            } else vv[kk] = -1e30f;
        }
#pragma unroll
        for (int o = 16; o; o >>= 1) mx = fmaxf(mx, __shfl_xor_sync(0xffffffffu, mx, o));
        float sum = 0.f;
#pragma unroll
        for (int kk = 0; kk < 4; kk++) { vv[kk] = __expf(vv[kk] - mx); sum += vv[kk]; }
#pragma unroll
        for (int o = 16; o; o >>= 1) sum += __shfl_xor_sync(0xffffffffu, sum, o);
        float inv = 1.f / sum;
#pragma unroll
        for (int kk = 0; kk < 4; kk++) {
            int n = lane + kk * 32;
            if (n < NNEI) {
                float w = vv[kk] * inv * s[SW + n];
                *reinterpret_cast<ull*>(s + AW + n * 8 + h * 2) = pk2(w, w);
            }
        }
    }
    __syncthreads();

    // ---- c-phase: thread (j-pair j2, n-quarter nq); aw pre-duplicated -> no movs ----
    {
        int j2 = tid >> 2, nq = tid & 3;
        ull a0 = 0, a1 = 0, a2 = 0, a3 = 0;   // heads 0..3, lanes = (j0, j1)
        int n0 = nq * 30;
#pragma unroll 6
        for (int ii = 0; ii < 30; ii++) {
            int n = n0 + ii;
            ull g = *reinterpret_cast<const ull*>(s + GG + n * 132 + j2 * 2);
            const ulonglong2* aw = reinterpret_cast<const ulonglong2*>(s + AW + n * 8);
            ulonglong2 w01 = aw[0], w23 = aw[1];
            a0 = ffma2(g, w01.x, a0);
            a1 = ffma2(g, w01.y, a1);
            a2 = ffma2(g, w23.x, a2);
            a3 = ffma2(g, w23.y, a3);
        }
        float f[8];
        upk2(a0, f[0], f[1]); upk2(a1, f[2], f[3]);
        upk2(a2, f[4], f[5]); upk2(a3, f[6], f[7]);
#pragma unroll
        for (int d = 2; d; d >>= 1)
#pragma unroll
            for (int q = 0; q < 8; q++)
                f[q] += __shfl_down_sync(0xffffffffu, f[q], d, 4);
        if (nq == 0) {
            int jA = j2 * 2;
            float* cb = d_C + (size_t)t * 512;
            *reinterpret_cast<ull*>(cb + 0 * 128 + jA) = pk2(f[0], f[1]);
            *reinterpret_cast<ull*>(cb + 1 * 128 + jA) = pk2(f[2], f[3]);
            *reinterpret_cast<ull*>(cb + 2 * 128 + jA) = pk2(f[4], f[5]);
            *reinterpret_cast<ull*>(cb + 3 * 128 + jA) = pk2(f[6], f[7]);
        }
    }
}

// ---------------- kernel 4: out = C @ Wfold + bh ----------------
// grid 256, 512 threads, 16 tokens per CTA
#define CT  0                    // [f][20] rows (16 t + 4 pad), 512*20 = 10240
#define OP  10240                // 4 * 16*128 = 8192 partials
#define OSMEMF 18432             // 73728 B
__global__ __launch_bounds__(512) void out_kernel(const float* __restrict__ bh,
                                                  float* __restrict__ out) {
    extern __shared__ float s[];
    const int t0  = blockIdx.x * 16;
    const int tid = threadIdx.x;

    // load C block [16][512] -> transposed smem [f][t] (rows padded to 20)
    for (int idx = tid; idx < 2048; idx += 512) {
        float4 v = reinterpret_cast<const float4*>(d_C)[(size_t)t0 * 128 + idx];
        int t = idx >> 7, f = (idx & 127) * 4;
        s[CT + (f + 0) * 20 + t] = v.x;
        s[CT + (f + 1) * 20 + t] = v.y;
        s[CT + (f + 2) * 20 + t] = v.z;
        s[CT + (f + 3) * 20 + t] = v.w;
    }
    __syncthreads();

    const int o = tid & 127, fg = tid >> 7;
    ull a[8];
#pragma unroll
    for (int k = 0; k < 8; k++) a[k] = 0;
    const float* wb = d_Wfold + (fg * 128) * 128 + o;
#pragma unroll 4
    for (int ff = 0; ff < 128; ff++) {
        float w = wb[ff * 128];
        ull w2 = pk2(w, w);
        const ulonglong2* cp = reinterpret_cast<const ulonglong2*>(s + CT + (fg * 128 + ff) * 20);
        ulonglong2 cA = cp[0], cB = cp[1];
        a[0] = ffma2(w2, cA.x, a[0]);
        a[1] = ffma2(w2, cA.y, a[1]);
        a[2] = ffma2(w2, cB.x, a[2]);
        a[3] = ffma2(w2, cB.y, a[3]);
        cA = cp[2]; cB = cp[3];
        a[4] = ffma2(w2, cA.x, a[4]);
        a[5] = ffma2(w2, cA.y, a[5]);
        a[6] = ffma2(w2, cB.x, a[6]);
        a[7] = ffma2(w2, cB.y, a[7]);
    }
#pragma unroll
    for (int k = 0; k < 8; k++) {
        float x, y; upk2(a[k], x, y);
        s[OP + fg * 2048 + (2 * k) * 128 + o]     = x;
        s[OP + fg * 2048 + (2 * k + 1) * 128 + o] = y;
    }
    __syncthreads();
    for (int idx = tid; idx < 2048; idx += 512) {
        int t = idx >> 7, oo = idx & 127;
        float v = bh[oo] + s[OP + idx] + s[OP + 2048 + idx]
                         + s[OP + 4096 + idx] + s[OP + 6144 + idx];
        out[(size_t)(t0 + t) * 128 + oo] = v;
    }
}

extern "C" void kernel_launch(void* const* d_in, const int* in_sizes, int n_in,
                              void* d_out, int out_size) {
    const float* g1  = (const float*)d_in[0];
    const float* gg1 = (const float*)d_in[1];
    // d_in[2] = nlist_mask: redundant (sw == uniform * mask)
    const float* sw  = (const float*)d_in[3];
    const float* Wq  = (const float*)d_in[4];
    const float* Wkv = (const float*)d_in[5];
    const float* Wh  = (const float*)d_in[6];
    const float* bh  = (const float*)d_in[7];
    float* out = (float*)d_out;

    const size_t ASMEM = (size_t)SMEMF * sizeof(float);   // 73632 B
    const size_t OSMEM = (size_t)OSMEMF * sizeof(float);  // 73728 B

    cudaFuncSetAttribute((const void*)atten_kernel,
                         cudaFuncAttributeMaxDynamicSharedMemorySize, (int)ASMEM);
    cudaFuncSetAttribute((const void*)out_kernel,
                         cudaFuncAttributeMaxDynamicSharedMemorySize, (int)OSMEM);

    prep_kernel<<<512, 256>>>(Wq, Wkv, Wh);
    qe_kernel<<<NLOC / 16, 512>>>(g1);
    atten_kernel<<<NLOC, 256, ASMEM>>>(gg1, sw);
    out_kernel<<<NLOC / 16, 512, OSMEM>>>(bh, out);
}